// round 7
// baseline (speedup 1.0000x reference)
#include <cuda_runtime.h>
#include <math.h>

#define NSAMP 1048576
#define NHOPS 1904                 // NSAMP/551 + 1
#define LBLK 16                    // output samples per sequential thread
#define IH 80                      // warmup (76) + FIR history (4)
#define ISTEPS (LBLK + IH)         // 96
#define NQUAD (ISTEPS / 4)         // 24
#define WQUAD (IH / 4)             // 20 warmup quads
#define BT 128                     // threads per block (4 warps)
#define BOUT (BT * LBLK)           // 2048 outputs per block
#define NB (NSAMP / BOUT)          // 512 blocks
#define HBUF (BOUT + IH)           // 2128 h1 samples needed
#define XBUF (HBUF + 15)           // 2143 real x samples staged
#define XSTG 2160                  // staged incl zero pad (ring refresh overreads)
#define FPL 23                     // FIR outputs per lane (96 lanes, 96*23 >= 2128)
#define KTAP 16
#define DPOS (1903.0f / 1048575.0f)

// ============================================================
// Single fused kernel
// ============================================================
__global__ void __launch_bounds__(BT) phaser(
    const float* __restrict__ x,
    const float* __restrict__ g1,   const float* __restrict__ g2,
    const float* __restrict__ depth,const float* __restrict__ bias,
    const float* __restrict__ om,   const float* __restrict__ phi,
    const float* __restrict__ rl,
    const float* __restrict__ Win,  const float* __restrict__ bin,
    const float* __restrict__ Wh,   const float* __restrict__ bh,
    const float* __restrict__ Wout, const float* __restrict__ bout,
    const float* __restrict__ bqdc, const float* __restrict__ bqff,
    const float* __restrict__ bqfb,
    float* __restrict__ out, int out_size)
{
    __shared__ float sX[2176];     // x stage (XSTG), later output stage (o+(o>>5))
    __shared__ float sH[2208];     // h1 (idx j+(j>>5))
    __shared__ float sC[80];       // 8 hop slots x 9 coefs {cb0..4, cd1..4}
    __shared__ float sW[612];      // Win 0 | bin 32 | Wh 48 | bh 560 | Wout 592 | bout 608
    __shared__ float sA[128];      // MLP activations ping
    __shared__ float sB[128];      // MLP activations pong

    int tid = threadIdx.x;
    int b   = blockIdx.x;
    int n0  = b * BOUT - IH;       // sample index of sH[0]
    float g1v = g1[0];

    // ---- phase 0: stage x (zero-padded) and MLP weights ----
    for (int j = tid; j < XSTG; j += BT) {
        int n = n0 - (KTAP - 1) + j;
        sX[j] = (n >= 0 && n < NSAMP && j < XBUF) ? x[n] : 0.f;
    }
    for (int j = tid; j < 32;  j += BT) sW[j]       = Win[j];
    for (int j = tid; j < 16;  j += BT) sW[32 + j]  = bin[j];
    for (int j = tid; j < 512; j += BT) sW[48 + j]  = Wh[j];
    for (int j = tid; j < 32;  j += BT) sW[560 + j] = bh[j];
    for (int j = tid; j < 16;  j += BT) sW[592 + j] = Wout[j];
    if (tid == 0) sW[608] = bout[0];

    int h_lo = (int)floorf((float)n0 * DPOS);
    if (h_lo < 0) h_lo = 0;
    __syncthreads();

    // ---- phase 1: warp 0 = 8 hop MLPs (4 lanes each); warps 1-3 = FIR ----
    if (tid < 32) {
        int hopi = tid >> 2, sub = tid & 3;
        int hop = h_lo + hopi; if (hop > NHOPS - 1) hop = NHOPS - 1;
        float tf = (float)hop;
        float r  = 1.f / (1.f + expf(-__ldg(&rl[0])));
        float amp = expf(tf * logf(r));
        float ph  = __ldg(&om[0]) * tf + __ldg(&phi[0]);
        float l0 = amp * cosf(ph), l1 = amp * sinf(ph);

        // input layer: 4 neurons per lane
#pragma unroll
        for (int q = 0; q < 4; q++) {
            int j = sub * 4 + q;
            sA[hopi * 16 + j] = tanhf(fmaf(l0, sW[j], fmaf(l1, sW[16 + j], sW[32 + j])));
        }
        __syncwarp();
        // hidden layer 0: sA -> sB ; hidden layer 1: sB -> sA
#pragma unroll
        for (int l = 0; l < 2; l++) {
            const float* src = l ? sB : sA;
            float*       dst = l ? sA : sB;
            float t0v, t1v, t2v, t3v;
            {
                float a0 = sW[560 + l * 16 + sub * 4 + 0];
                float a1 = sW[560 + l * 16 + sub * 4 + 1];
                float a2 = sW[560 + l * 16 + sub * 4 + 2];
                float a3 = sW[560 + l * 16 + sub * 4 + 3];
#pragma unroll
                for (int i = 0; i < 16; i++) {
                    float hi = src[hopi * 16 + i];
                    const float* wrow = &sW[48 + l * 256 + i * 16 + sub * 4];
                    a0 = fmaf(hi, wrow[0], a0);
                    a1 = fmaf(hi, wrow[1], a1);
                    a2 = fmaf(hi, wrow[2], a2);
                    a3 = fmaf(hi, wrow[3], a3);
                }
                t0v = tanhf(a0); t1v = tanhf(a1); t2v = tanhf(a2); t3v = tanhf(a3);
            }
            __syncwarp();
            dst[hopi * 16 + sub * 4 + 0] = t0v;
            dst[hopi * 16 + sub * 4 + 1] = t1v;
            dst[hopi * 16 + sub * 4 + 2] = t2v;
            dst[hopi * 16 + sub * 4 + 3] = t3v;
            __syncwarp();
        }
        if (sub == 0) {
            float acc = sW[608];
#pragma unroll
            for (int i = 0; i < 16; i++) acc = fmaf(sA[hopi * 16 + i], sW[592 + i], acc);
            float ws = tanhf(acc);

            float dd = __ldg(&bias[0]) + __ldg(&depth[0]) * 0.5f * (1.f + ws);
            float td = tanf(dd);
            float p  = tanhf((1.f - td) / (1.f + td));

            float p2 = p * p, p3 = p2 * p, p4 = p2 * p2;
            float bap[5] = { p4, -4.f * p3, 6.f * p2, -4.f * p, 1.f };
            float aap[5] = { 1.f, -4.f * p, 6.f * p2, -4.f * p3, p4 };
            float ga  = fabsf(__ldg(&g2[0]));
            float inv = 1.f / (1.f - ga * p4);
            float* cc = &sC[hopi * 9];
#pragma unroll
            for (int k = 0; k < 5; k++) cc[k] = bap[k] * inv;
#pragma unroll
            for (int k = 1; k < 5; k++) cc[4 + k] = (aap[k] - ga * bap[k]) * inv;

            if (out_size >= NSAMP + NHOPS) out[NSAMP + hop] = p;
        }
    } else {
        // ---- FIR: 96 lanes, 23 outputs each, rolling 16-reg window ----
        int f  = tid - 32;
        int o0 = f * FPL;
        if (o0 < HBUF) {
            float a1c = 2.f * tanhf(__ldg(&bqfb[0]));
            float a2c = ((2.f - fabsf(a1c)) * tanhf(__ldg(&bqfb[1])) + fabsf(a1c)) * 0.5f;
            float bb0 = __ldg(&bqdc[0]), bb1 = __ldg(&bqff[0]), bb2 = __ldg(&bqff[1]);
            float tp[KTAP];
            float hm1 = 0.f, hm2 = 0.f;
#pragma unroll
            for (int k = 0; k < KTAP; k++) {
                float ha = (k == 0 ? 1.f : 0.f) - a1c * hm1 - a2c * hm2;
                tp[k] = bb0 * ha + bb1 * hm1 + bb2 * hm2;
                hm2 = hm1; hm1 = ha;
            }
            int jend = min(o0 + FPL, HBUF);
            float w[16];
#pragma unroll
            for (int k = 0; k < 16; k++) w[k] = sX[o0 + k];
#pragma unroll
            for (int s = 0; s < 16; s++) {
                int jj = o0 + s;
                if (jj < jend) {
                    float acc = 0.f;
#pragma unroll
                    for (int m = 0; m < 16; m++)
                        acc = fmaf(tp[15 - m], w[(s + m) & 15], acc);
                    sH[jj + (jj >> 5)] = acc;
                    w[s] = sX[jj + 16];
                }
            }
#pragma unroll
            for (int s = 0; s < FPL - 16; s++) {
                int jj = o0 + 16 + s;
                if (jj < jend) {
                    float acc = 0.f;
#pragma unroll
                    for (int m = 0; m < 16; m++)
                        acc = fmaf(tp[15 - m], w[(s + m) & 15], acc);
                    sH[jj + (jj >> 5)] = acc;
                    w[s] = sX[jj + 16];
                }
            }
        }
    }
    __syncthreads();

    // ---- phase 2: TV-FIR + order-4 TV-IIR recurrence ----
    int   li0 = tid * LBLK;
    float fi  = (float)(n0 + li0);
    int i0 = (int)floorf(fi * DPOS);
    i0 = max(0, min(i0, NHOPS - 2));
    float i0f = (float)i0;

    float b0,b1,b2,b3,b4,bd1,bd2,bd3,bd4;
    float d0,d1,d2,d3,d4,dd1,dd2,dd3,dd4;
#define RELOAD() do {                                              \
        const float* c0 = sC + (i0 - h_lo) * 9;                    \
        b0=c0[0]; b1=c0[1]; b2=c0[2]; b3=c0[3]; b4=c0[4];          \
        bd1=c0[5]; bd2=c0[6]; bd3=c0[7]; bd4=c0[8];                \
        d0=c0[9]-b0; d1=c0[10]-b1; d2=c0[11]-b2;                   \
        d3=c0[12]-b3; d4=c0[13]-b4;                                \
        dd1=c0[14]-bd1; dd2=c0[15]-bd2;                            \
        dd3=c0[16]-bd3; dd4=c0[17]-bd4;                            \
    } while (0)
    RELOAD();

    float h0 = 0.f, h1v = 0.f, h2 = 0.f, h3 = 0.f;
    float y1 = 0.f, y2 = 0.f, y3 = 0.f, y4 = 0.f;

    // warmup: coefficients frozen per quad (error decays before live region)
#pragma unroll 1
    for (int g = 0; g < WQUAD; g++) {
        float frac = fmaf(fi, DPOS, -i0f);
        if (frac >= 1.f && i0 < NHOPS - 2) { i0++; i0f += 1.f; frac -= 1.f; RELOAD(); }
        float cb0 = fmaf(frac, d0, b0);
        float cb1 = fmaf(frac, d1, b1);
        float cb2 = fmaf(frac, d2, b2);
        float cb3 = fmaf(frac, d3, b3);
        float cb4 = fmaf(frac, d4, b4);
        float cd1 = fmaf(frac, dd1, bd1);
        float cd2 = fmaf(frac, dd2, bd2);
        float cd3 = fmaf(frac, dd3, bd3);
        float cd4 = fmaf(frac, dd4, bd4);
#pragma unroll
        for (int s = 0; s < 4; s++) {
            int li = li0 + g * 4 + s;
            float hn = sH[li + (li >> 5)];
            float v = cb0 * hn;
            v = fmaf(cb1, h0, v); v = fmaf(cb2, h1v, v);
            v = fmaf(cb3, h2, v); v = fmaf(cb4, h3, v);
            float a = fmaf(-cd4, y4, v);
            a = fmaf(-cd3, y3, a); a = fmaf(-cd2, y2, a);
            float y = fmaf(-cd1, y1, a);
            y4 = y3; y3 = y2; y2 = y1; y1 = y;
            h3 = h2; h2 = h1v; h1v = h0; h0 = hn;
        }
        fi += 4.f;
    }
    // live: per-sample interpolation (reference-exact)
#pragma unroll 1
    for (int g = WQUAD; g < NQUAD; g++) {
        float frac = fmaf(fi, DPOS, -i0f);
        if (frac >= 1.f && i0 < NHOPS - 2) { i0++; i0f += 1.f; frac -= 1.f; RELOAD(); }
#pragma unroll
        for (int s = 0; s < 4; s++) {
            int li = li0 + g * 4 + s;
            float hn = sH[li + (li >> 5)];
            float cb0 = fmaf(frac, d0, b0);
            float cb1 = fmaf(frac, d1, b1);
            float cb2 = fmaf(frac, d2, b2);
            float cb3 = fmaf(frac, d3, b3);
            float cb4 = fmaf(frac, d4, b4);
            float cd1 = fmaf(frac, dd1, bd1);
            float cd2 = fmaf(frac, dd2, bd2);
            float cd3 = fmaf(frac, dd3, bd3);
            float cd4 = fmaf(frac, dd4, bd4);
            float v = cb0 * hn;
            v = fmaf(cb1, h0, v); v = fmaf(cb2, h1v, v);
            v = fmaf(cb3, h2, v); v = fmaf(cb4, h3, v);
            float a = fmaf(-cd4, y4, v);
            a = fmaf(-cd3, y3, a); a = fmaf(-cd2, y2, a);
            float y = fmaf(-cd1, y1, a);
            y4 = y3; y3 = y2; y2 = y1; y1 = y;
            h3 = h2; h2 = h1v; h1v = h0; h0 = hn;
            int o = li - IH;
            sX[o + (o >> 5)] = fmaf(g1v, hn, y);
            frac += DPOS;
        }
        fi += 4.f;
    }
#undef RELOAD

    __syncthreads();
    int base = b * BOUT;
    for (int j = tid; j < BOUT; j += BT)
        out[base + j] = sX[j + (j >> 5)];
}

// ============================================================
extern "C" void kernel_launch(void* const* d_in, const int* in_sizes, int n_in,
                              void* d_out, int out_size)
{
    const float* x    = (const float*)d_in[0];
    const float* g1   = (const float*)d_in[1];
    const float* g2   = (const float*)d_in[2];
    const float* dep  = (const float*)d_in[3];
    const float* bia  = (const float*)d_in[4];
    const float* om   = (const float*)d_in[5];
    const float* phi  = (const float*)d_in[6];
    const float* rl   = (const float*)d_in[7];
    const float* Win  = (const float*)d_in[8];
    const float* bin  = (const float*)d_in[9];
    const float* Wh   = (const float*)d_in[10];
    const float* bh   = (const float*)d_in[11];
    const float* Wout = (const float*)d_in[12];
    const float* bout = (const float*)d_in[13];
    const float* bqdc = (const float*)d_in[14];
    const float* bqff = (const float*)d_in[15];
    const float* bqfb = (const float*)d_in[16];
    float* out = (float*)d_out;

    phaser<<<NB, BT>>>(x, g1, g2, dep, bia, om, phi, rl,
                       Win, bin, Wh, bh, Wout, bout, bqdc, bqff, bqfb,
                       out, out_size);
}